// round 9
// baseline (speedup 1.0000x reference)
#include <cuda_runtime.h>
#include <math.h>

#define HID   256
#define HEADS 8
#define MAXN  20000
#define MAXE  320000

// ---------------- static device scratch (no runtime allocation) ----------------
__device__ float g_q[MAXN * HID];     // Q projection (pre-scaled), layout [n][d*8+h]
__device__ float g_k[MAXN * HID];
__device__ float g_v[MAXN * HID];
__device__ float g_acc[MAXN * HID];   // attention output before Wo
__device__ float g_s[(size_t)MAXE * HEADS];  // per-edge per-head scores (CSR-permuted order)
__device__ int   g_rowptr[MAXN + 1];
__device__ int   g_cursor[MAXN];
__device__ int   g_pcol[MAXE];        // col (src node) per CSR-permuted edge

// ---------------- CSR build ----------------
__global__ void k_zero(int n) {
    int i = blockIdx.x * blockDim.x + threadIdx.x;
    if (i < n) g_cursor[i] = 0;
}

__global__ void k_hist(const int* __restrict__ rows, int e) {
    int i = blockIdx.x * blockDim.x + threadIdx.x;
    if (i < e) atomicAdd(&g_cursor[rows[i]], 1);
}

// single-block chunked Hillis-Steele scan: counts (in g_cursor) -> g_rowptr, then cursor = rowptr
__global__ void k_scan(int n) {
    __shared__ int sh[1024];
    int tid = threadIdx.x;
    int carry = 0;
    int nch = (n + 1023) >> 10;
    for (int c = 0; c < nch; ++c) {
        int i = (c << 10) + tid;
        int v = (i < n) ? g_cursor[i] : 0;
        __syncthreads();   // protect sh from previous iteration readers
        sh[tid] = v;
        __syncthreads();
        #pragma unroll
        for (int off = 1; off < 1024; off <<= 1) {
            int t = 0;
            if (tid >= off) t = sh[tid - off];
            __syncthreads();
            if (tid >= off) sh[tid] += t;
            __syncthreads();
        }
        if (i < n) g_rowptr[i + 1] = carry + sh[tid];
        carry += sh[1023];
    }
    if (tid == 0) g_rowptr[0] = 0;
    __syncthreads();
    for (int i = tid; i < n; i += 1024) g_cursor[i] = g_rowptr[i];
}

__global__ void k_scatter(const int* __restrict__ rows, const int* __restrict__ cols, int e) {
    int i = blockIdx.x * blockDim.x + threadIdx.x;
    if (i < e) {
        int r = rows[i];
        int pos = atomicAdd(&g_cursor[r], 1);
        g_pcol[pos] = cols[i];
    }
}

// ---------------- packed f32x2 helpers ----------------
__device__ __forceinline__ unsigned long long pack2(float a) {
    unsigned long long r;
    unsigned int u = __float_as_uint(a);
    asm("mov.b64 %0, {%1, %1};" : "=l"(r) : "r"(u));
    return r;
}
__device__ __forceinline__ void fma2(unsigned long long& d, unsigned long long a, unsigned long long b) {
    asm("fma.rn.f32x2 %0, %1, %2, %0;" : "+l"(d) : "l"(a), "l"(b));
}
__device__ __forceinline__ float2 unpack2(unsigned long long v) {
    unsigned int lo, hi;
    asm("mov.b64 {%0, %1}, %2;" : "=r"(lo), "=r"(hi) : "l"(v));
    return make_float2(__uint_as_float(lo), __uint_as_float(hi));
}

// ---------------- GEMM core: C = (A[M,256] @ B[256,256] + bias) * scale ----------------
// 128x128 tile, BK=16, 256 threads, 8x8 micro-tile (4+4 split), f32x2 packed FMA.
__device__ __forceinline__ void gemm_core(
    float (*As)[132], float (*Bs)[132],
    const float* __restrict__ A, const float* __restrict__ B,
    const float* __restrict__ bias, float* __restrict__ C,
    int M, float scale)
{
    const int tid = threadIdx.x;
    const int tx  = tid & 15;
    const int ty  = tid >> 4;
    const int m0  = blockIdx.y * 128;
    const int n0  = blockIdx.x * 128;

    unsigned long long acc[8][4];
    #pragma unroll
    for (int i = 0; i < 8; ++i)
        #pragma unroll
        for (int j = 0; j < 4; ++j) acc[i][j] = 0ull;

    for (int k0 = 0; k0 < HID; k0 += 16) {
        // A tile 128x16 -> transposed smem
        #pragma unroll
        for (int t = 0; t < 2; ++t) {
            int i4 = tid + t * 256;
            int ar = i4 >> 2;
            int ak = (i4 & 3) << 2;
            float4 f = make_float4(0.f, 0.f, 0.f, 0.f);
            int grow = m0 + ar;
            if (grow < M) f = *(const float4*)(A + (size_t)grow * HID + k0 + ak);
            As[ak + 0][ar] = f.x; As[ak + 1][ar] = f.y;
            As[ak + 2][ar] = f.z; As[ak + 3][ar] = f.w;
        }
        // B tile 16x128
        #pragma unroll
        for (int t = 0; t < 2; ++t) {
            int i4 = tid + t * 256;
            int br = i4 >> 5;
            int bc = (i4 & 31) << 2;
            *(float4*)&Bs[br][bc] = *(const float4*)(B + (size_t)(k0 + br) * HID + n0 + bc);
        }
        __syncthreads();
        #pragma unroll
        for (int k = 0; k < 16; ++k) {
            float a[8];
            *(float4*)&a[0] = *(const float4*)&As[k][ty * 4];
            *(float4*)&a[4] = *(const float4*)&As[k][ty * 4 + 64];
            unsigned long long b2[4];
            const unsigned long long* bp0 = (const unsigned long long*)&Bs[k][tx * 4];
            const unsigned long long* bp1 = (const unsigned long long*)&Bs[k][tx * 4 + 64];
            b2[0] = bp0[0]; b2[1] = bp0[1];
            b2[2] = bp1[0]; b2[3] = bp1[1];
            #pragma unroll
            for (int i = 0; i < 8; ++i) {
                unsigned long long a2 = pack2(a[i]);
                fma2(acc[i][0], a2, b2[0]);
                fma2(acc[i][1], a2, b2[1]);
                fma2(acc[i][2], a2, b2[2]);
                fma2(acc[i][3], a2, b2[3]);
            }
        }
        __syncthreads();
    }

    float bb[8];
    *(float4*)&bb[0] = *(const float4*)(bias + n0 + tx * 4);
    *(float4*)&bb[4] = *(const float4*)(bias + n0 + tx * 4 + 64);
    #pragma unroll
    for (int i = 0; i < 8; ++i) {
        int row = m0 + ty * 4 + (i & 3) + (i >> 2) * 64;
        if (row >= M) continue;
        float2 p0 = unpack2(acc[i][0]);
        float2 p1 = unpack2(acc[i][1]);
        float4 o;
        o.x = (p0.x + bb[0]) * scale;
        o.y = (p0.y + bb[1]) * scale;
        o.z = (p1.x + bb[2]) * scale;
        o.w = (p1.y + bb[3]) * scale;
        *(float4*)(C + (size_t)row * HID + n0 + tx * 4) = o;
        float2 p2 = unpack2(acc[i][2]);
        float2 p3 = unpack2(acc[i][3]);
        o.x = (p2.x + bb[4]) * scale;
        o.y = (p2.y + bb[5]) * scale;
        o.z = (p3.x + bb[6]) * scale;
        o.w = (p3.y + bb[7]) * scale;
        *(float4*)(C + (size_t)row * HID + n0 + tx * 4 + 64) = o;
    }
}

__global__ void __launch_bounds__(256, 2) k_gemm_qkv(
    const float* __restrict__ h,
    const float* __restrict__ Wq, const float* __restrict__ bq,
    const float* __restrict__ Wk, const float* __restrict__ bk,
    const float* __restrict__ Wv, const float* __restrict__ bv,
    int M)
{
    __shared__ float As[16][132];
    __shared__ float Bs[16][132];
    if (blockIdx.z == 0)
        gemm_core(As, Bs, h, Wq, bq, g_q, M, 0.17677669529663689f);  // HD^-0.5
    else if (blockIdx.z == 1)
        gemm_core(As, Bs, h, Wk, bk, g_k, M, 1.0f);
    else
        gemm_core(As, Bs, h, Wv, bv, g_v, M, 1.0f);
}

__global__ void __launch_bounds__(256, 2) k_gemm_out(
    const float* __restrict__ Wo, const float* __restrict__ bo,
    float* __restrict__ out, int M)
{
    __shared__ float As[16][132];
    __shared__ float Bs[16][132];
    gemm_core(As, Bs, g_acc, Wo, bo, out, M, 1.0f);
}

// ---------------- fused SDDMM + softmax + SPMM : one warp per row ----------------
// Layout trick: element m of a 256-float node row has head = m%8. Lane l owns
// elements l, l+32, ..., l+224 -> head l%8 constant per lane.
__global__ void k_row(int n) {
    int warp = (blockIdx.x * blockDim.x + threadIdx.x) >> 5;
    int lane = threadIdx.x & 31;
    if (warp >= n) return;
    int row = warp;
    int p0 = g_rowptr[row];
    int p1 = g_rowptr[row + 1];

    // q row (already scaled) in registers
    const float* qp = g_q + (size_t)row * HID + lane;
    float qr[8];
    #pragma unroll
    for (int j = 0; j < 8; ++j) qr[j] = qp[32 * j];

    // pass 0: per-edge scores (per-head dot via butterfly) + online softmax m,z
    float m = -INFINITY, z = 0.f;
    for (int p = p0; p < p1; ++p) {
        int col = g_pcol[p];
        const float* kp = g_k + (size_t)col * HID + lane;
        float part = 0.f;
        #pragma unroll
        for (int j = 0; j < 8; ++j) part = fmaf(qr[j], kp[32 * j], part);
        part += __shfl_xor_sync(0xffffffffu, part, 8);
        part += __shfl_xor_sync(0xffffffffu, part, 16);
        // now all lanes hold the dot for head (lane % 8)
        if (lane < 8) g_s[(size_t)p * 8 + lane] = part;
        float mn = fmaxf(m, part);
        z = z * __expf(m - mn) + __expf(part - mn);
        m = mn;
    }
    __syncwarp();  // order g_s writes before re-reads below

    float zinv = (z > 0.f) ? (1.0f / z) : 0.0f;
    float acc[8];
    #pragma unroll
    for (int j = 0; j < 8; ++j) acc[j] = 0.f;

    // pass 1: weighted gather of v
    for (int p = p0; p < p1; ++p) {
        float s = g_s[(size_t)p * 8 + (lane & 7)];
        float w = __expf(s - m) * zinv;
        int col = g_pcol[p];
        const float* vp = g_v + (size_t)col * HID + lane;
        #pragma unroll
        for (int j = 0; j < 8; ++j) acc[j] = fmaf(w, vp[32 * j], acc[j]);
    }

    float* op = g_acc + (size_t)row * HID + lane;
    #pragma unroll
    for (int j = 0; j < 8; ++j) op[32 * j] = acc[j];
}

// ---------------- launch ----------------
extern "C" void kernel_launch(void* const* d_in, const int* in_sizes, int n_in,
                              void* d_out, int out_size)
{
    const float* h  = (const float*)d_in[0];
    const float* Wq = (const float*)d_in[1];
    const float* bq = (const float*)d_in[2];
    const float* Wk = (const float*)d_in[3];
    const float* bk = (const float*)d_in[4];
    const float* Wv = (const float*)d_in[5];
    const float* bv = (const float*)d_in[6];
    const float* Wo = (const float*)d_in[7];
    const float* bo = (const float*)d_in[8];
    const int* rows = (const int*)d_in[9];
    const int* cols = (const int*)d_in[10];
    (void)n_in; (void)out_size;

    int n = in_sizes[0] / HID;   // 20000
    int e = in_sizes[9];         // 320000
    float* out = (float*)d_out;

    // CSR build
    k_zero<<<(n + 255) / 256, 256>>>(n);
    k_hist<<<(e + 255) / 256, 256>>>(rows, e);
    k_scan<<<1, 1024>>>(n);
    k_scatter<<<(e + 255) / 256, 256>>>(rows, cols, e);

    // QKV projections (one launch, z selects weight)
    dim3 gq(HID / 128, (n + 127) / 128, 3);
    k_gemm_qkv<<<gq, 256>>>(h, Wq, bq, Wk, bk, Wv, bv, n);

    // fused sparse attention
    k_row<<<(n * 32 + 255) / 256, 256>>>(n);

    // output projection
    dim3 go(HID / 128, (n + 127) / 128, 1);
    k_gemm_out<<<go, 256>>>(Wo, bo, out, n);
}

// round 11
// speedup vs baseline: 1.3563x; 1.3563x over previous
#include <cuda_runtime.h>
#include <cuda_fp16.h>
#include <math.h>
#include <stdint.h>

#define HID   256
#define HEADS 8
#define MAXN  20000
#define MAXE  320000

// ---------------- static device scratch (no runtime allocation) ----------------
__device__ float g_q[MAXN * HID];          // Q projection (pre-scaled)
__device__ float g_k[MAXN * HID];
__device__ float g_v[MAXN * HID];
__device__ __half g_hhi[MAXN * HID];       // h split into fp16 hi/lo
__device__ __half g_hlo[MAXN * HID];
__device__ __half g_ahi[MAXN * HID];       // attention output split hi/lo
__device__ __half g_alo[MAXN * HID];
__device__ __half g_wthi[4 * HID * HID];   // W^T hi  (Wq,Wk,Wv,Wo), layout [z][n][k]
__device__ __half g_wtlo[4 * HID * HID];   // W^T lo
__device__ float g_s[(size_t)MAXE * HEADS];
__device__ int   g_rowptr[MAXN + 1];
__device__ int   g_cursor[MAXN];
__device__ int   g_pcol[MAXE];

// ---------------- CSR build ----------------
__global__ void k_zero(int n) {
    int i = blockIdx.x * blockDim.x + threadIdx.x;
    if (i < n) g_cursor[i] = 0;
}
__global__ void k_hist(const int* __restrict__ rows, int e) {
    int i = blockIdx.x * blockDim.x + threadIdx.x;
    if (i < e) atomicAdd(&g_cursor[rows[i]], 1);
}
__global__ void k_scan(int n) {
    __shared__ int sh[1024];
    int tid = threadIdx.x;
    int carry = 0;
    int nch = (n + 1023) >> 10;
    for (int c = 0; c < nch; ++c) {
        int i = (c << 10) + tid;
        int v = (i < n) ? g_cursor[i] : 0;
        __syncthreads();
        sh[tid] = v;
        __syncthreads();
        #pragma unroll
        for (int off = 1; off < 1024; off <<= 1) {
            int t = 0;
            if (tid >= off) t = sh[tid - off];
            __syncthreads();
            if (tid >= off) sh[tid] += t;
            __syncthreads();
        }
        if (i < n) g_rowptr[i + 1] = carry + sh[tid];
        carry += sh[1023];
    }
    if (tid == 0) g_rowptr[0] = 0;
    __syncthreads();
    for (int i = tid; i < n; i += 1024) g_cursor[i] = g_rowptr[i];
}
__global__ void k_scatter(const int* __restrict__ rows, const int* __restrict__ cols, int e) {
    int i = blockIdx.x * blockDim.x + threadIdx.x;
    if (i < e) {
        int r = rows[i];
        int pos = atomicAdd(&g_cursor[r], 1);
        g_pcol[pos] = cols[i];
    }
}

// ---------------- precision-split conversions (fp16 hi/lo) ----------------
__global__ void k_conv_h(const float* __restrict__ h, int total) {
    int i = blockIdx.x * blockDim.x + threadIdx.x;
    if (i < total) {
        float x = h[i];
        __half hi = __float2half_rn(x);
        g_hhi[i] = hi;
        g_hlo[i] = __float2half_rn(x - __half2float(hi));
    }
}
// W^T split: Wt[z][n][k] = split(W[k][n])
__global__ void k_conv_w(const float* __restrict__ Wq, const float* __restrict__ Wk,
                         const float* __restrict__ Wv, const float* __restrict__ Wo) {
    int z = blockIdx.y;
    const float* W = (z == 0) ? Wq : (z == 1) ? Wk : (z == 2) ? Wv : Wo;
    int i = blockIdx.x * blockDim.x + threadIdx.x;   // i = k*256 + n (coalesced read)
    int kk = i >> 8, nn = i & 255;
    float x = W[i];
    __half hi = __float2half_rn(x);
    size_t o = (size_t)z * HID * HID + (size_t)nn * HID + kk;
    g_wthi[o] = hi;
    g_wtlo[o] = __float2half_rn(x - __half2float(hi));
}

// ---------------- mma.sync fp16-split GEMM ----------------
// C[M,256] = A[M,256] @ W[256,256] + bias, A/W given as fp16 hi+lo:
//   D = Ahi*Bhi + Alo*Bhi + Ahi*Blo  (fp32 accumulate, ~22-bit effective mantissa)
// CTA tile 128x128 (grid.x picks the N half), 8 warps, warp tile 32x64.
// K processed in 4 chunks of 64 through padded smem (stride 72 halves).

#define LDA 72   // smem row stride in halves (conflict-free for frag LDS pattern)
static const int GEMM_SMEM_DYN = 4 * 128 * LDA * sizeof(__half);  // 73728 B

__device__ __forceinline__ void mma16816(float* d, const uint32_t* a, const uint32_t* b) {
    asm volatile(
        "mma.sync.aligned.m16n8k16.row.col.f32.f16.f16.f32 "
        "{%0,%1,%2,%3}, {%4,%5,%6,%7}, {%8,%9}, {%0,%1,%2,%3};"
        : "+f"(d[0]), "+f"(d[1]), "+f"(d[2]), "+f"(d[3])
        : "r"(a[0]), "r"(a[1]), "r"(a[2]), "r"(a[3]), "r"(b[0]), "r"(b[1]));
}

__device__ __forceinline__ void gemm_mma_body(
    __half* sm,
    const __half* __restrict__ Ahi, const __half* __restrict__ Alo,
    const __half* __restrict__ Bhi, const __half* __restrict__ Blo,
    const float* __restrict__ bias, float* __restrict__ C,
    int M, float scale, int m0, int n0)
{
    __half* sAhi = sm;
    __half* sAlo = sm + 128 * LDA;
    __half* sBhi = sm + 2 * 128 * LDA;
    __half* sBlo = sm + 3 * 128 * LDA;

    const int tid  = threadIdx.x;
    const int wid  = tid >> 5;
    const int lane = tid & 31;
    const int g    = lane >> 2;      // group id 0..7
    const int t    = lane & 3;       // thread in group
    const int wm   = (wid & 3) * 32; // warp m offset in CTA tile
    const int wn   = (wid >> 2) * 64;// warp n offset in CTA tile

    float acc[2][8][4];
    #pragma unroll
    for (int i = 0; i < 2; ++i)
        #pragma unroll
        for (int j = 0; j < 8; ++j)
            #pragma unroll
            for (int r = 0; r < 4; ++r) acc[i][j][r] = 0.f;

    for (int c = 0; c < 4; ++c) {
        int k0 = c * 64;
        // load A tiles (128 rows x 64 halves) hi+lo
        #pragma unroll
        for (int it = 0; it < 4; ++it) {
            int i = tid + it * 256;
            int r = i >> 3, c8 = i & 7;
            int gr = m0 + r;
            uint4 vh = make_uint4(0, 0, 0, 0), vl = vh;
            if (gr < M) {
                vh = *(const uint4*)(Ahi + (size_t)gr * HID + k0 + c8 * 8);
                vl = *(const uint4*)(Alo + (size_t)gr * HID + k0 + c8 * 8);
            }
            *(uint4*)(sAhi + r * LDA + c8 * 8) = vh;
            *(uint4*)(sAlo + r * LDA + c8 * 8) = vl;
        }
        // load B tiles (128 n-rows x 64 halves) hi+lo
        #pragma unroll
        for (int it = 0; it < 4; ++it) {
            int i = tid + it * 256;
            int r = i >> 3, c8 = i & 7;
            uint4 vh = *(const uint4*)(Bhi + (size_t)(n0 + r) * HID + k0 + c8 * 8);
            uint4 vl = *(const uint4*)(Blo + (size_t)(n0 + r) * HID + k0 + c8 * 8);
            *(uint4*)(sBhi + r * LDA + c8 * 8) = vh;
            *(uint4*)(sBlo + r * LDA + c8 * 8) = vl;
        }
        __syncthreads();

        #pragma unroll
        for (int ks = 0; ks < 4; ++ks) {
            int kk = ks * 16;
            uint32_t ahi[2][4], alo[2][4];
            #pragma unroll
            for (int i = 0; i < 2; ++i) {
                int rb = wm + i * 16 + g;
                const __half* ph = sAhi + rb * LDA + kk + t * 2;
                const __half* pl = sAlo + rb * LDA + kk + t * 2;
                ahi[i][0] = *(const uint32_t*)(ph);
                ahi[i][1] = *(const uint32_t*)(ph + 8 * LDA);
                ahi[i][2] = *(const uint32_t*)(ph + 8);
                ahi[i][3] = *(const uint32_t*)(ph + 8 * LDA + 8);
                alo[i][0] = *(const uint32_t*)(pl);
                alo[i][1] = *(const uint32_t*)(pl + 8 * LDA);
                alo[i][2] = *(const uint32_t*)(pl + 8);
                alo[i][3] = *(const uint32_t*)(pl + 8 * LDA + 8);
            }
            #pragma unroll
            for (int j = 0; j < 8; ++j) {
                int nb = wn + j * 8 + g;
                const __half* ph = sBhi + nb * LDA + kk + t * 2;
                const __half* pl = sBlo + nb * LDA + kk + t * 2;
                uint32_t bhi[2], blo[2];
                bhi[0] = *(const uint32_t*)(ph);
                bhi[1] = *(const uint32_t*)(ph + 8);
                blo[0] = *(const uint32_t*)(pl);
                blo[1] = *(const uint32_t*)(pl + 8);
                #pragma unroll
                for (int i = 0; i < 2; ++i) {
                    mma16816(acc[i][j], ahi[i], bhi);
                    mma16816(acc[i][j], alo[i], bhi);
                    mma16816(acc[i][j], ahi[i], blo);
                }
            }
        }
        __syncthreads();
    }

    // epilogue: d0,d1 -> (row g, cols t*2,t*2+1); d2,d3 -> row g+8
    #pragma unroll
    for (int i = 0; i < 2; ++i) {
        int r0 = m0 + wm + i * 16 + g;
        #pragma unroll
        for (int j = 0; j < 8; ++j) {
            int col = n0 + wn + j * 8 + t * 2;
            float b0 = bias[col], b1 = bias[col + 1];
            if (r0 < M) {
                float2 o = make_float2((acc[i][j][0] + b0) * scale,
                                       (acc[i][j][1] + b1) * scale);
                *(float2*)(C + (size_t)r0 * HID + col) = o;
            }
            if (r0 + 8 < M) {
                float2 o = make_float2((acc[i][j][2] + b0) * scale,
                                       (acc[i][j][3] + b1) * scale);
                *(float2*)(C + (size_t)(r0 + 8) * HID + col) = o;
            }
        }
    }
}

__global__ void __launch_bounds__(256, 2) k_gemm_qkv_mma(
    const float* __restrict__ bq, const float* __restrict__ bk,
    const float* __restrict__ bv, int M)
{
    extern __shared__ __half sm[];
    int z = blockIdx.z;
    const __half* Bhi = g_wthi + (size_t)z * HID * HID;
    const __half* Blo = g_wtlo + (size_t)z * HID * HID;
    const float* bias = (z == 0) ? bq : (z == 1) ? bk : bv;
    float* C = (z == 0) ? g_q : (z == 1) ? g_k : g_v;
    float scale = (z == 0) ? 0.17677669529663689f : 1.0f;   // HD^-0.5 folded into Q
    gemm_mma_body(sm, g_hhi, g_hlo, Bhi, Blo, bias, C, M, scale,
                  blockIdx.y * 128, blockIdx.x * 128);
}

__global__ void __launch_bounds__(256, 2) k_gemm_out_mma(
    const float* __restrict__ bo, float* __restrict__ out, int M)
{
    extern __shared__ __half sm[];
    gemm_mma_body(sm, g_ahi, g_alo,
                  g_wthi + 3 * HID * HID, g_wtlo + 3 * HID * HID,
                  bo, out, M, 1.0f, blockIdx.y * 128, blockIdx.x * 128);
}

// ---------------- fused SDDMM + softmax + SPMM : one warp per row ----------------
// Layout trick: element m of a 256-float node row has head = m%8. Lane l owns
// elements l, l+32, ..., l+224 -> head l%8 constant per lane.
__global__ void k_row(int n) {
    int warp = (blockIdx.x * blockDim.x + threadIdx.x) >> 5;
    int lane = threadIdx.x & 31;
    if (warp >= n) return;
    int row = warp;
    int p0 = g_rowptr[row];
    int p1 = g_rowptr[row + 1];

    const float* qp = g_q + (size_t)row * HID + lane;
    float qr[8];
    #pragma unroll
    for (int j = 0; j < 8; ++j) qr[j] = qp[32 * j];

    float m = -INFINITY, z = 0.f;
    for (int p = p0; p < p1; ++p) {
        int col = g_pcol[p];
        const float* kp = g_k + (size_t)col * HID + lane;
        float part = 0.f;
        #pragma unroll
        for (int j = 0; j < 8; ++j) part = fmaf(qr[j], kp[32 * j], part);
        part += __shfl_xor_sync(0xffffffffu, part, 8);
        part += __shfl_xor_sync(0xffffffffu, part, 16);
        if (lane < 8) g_s[(size_t)p * 8 + lane] = part;
        float mn = fmaxf(m, part);
        z = z * __expf(m - mn) + __expf(part - mn);
        m = mn;
    }
    __syncwarp();

    float zinv = (z > 0.f) ? (1.0f / z) : 0.0f;
    float acc[8];
    #pragma unroll
    for (int j = 0; j < 8; ++j) acc[j] = 0.f;

    for (int p = p0; p < p1; ++p) {
        float s = g_s[(size_t)p * 8 + (lane & 7)];
        float w = __expf(s - m) * zinv;
        int col = g_pcol[p];
        const float* vp = g_v + (size_t)col * HID + lane;
        #pragma unroll
        for (int j = 0; j < 8; ++j) acc[j] = fmaf(w, vp[32 * j], acc[j]);
    }

    // write fp16 hi/lo split directly for the out-projection MMA
    #pragma unroll
    for (int j = 0; j < 8; ++j) {
        float a = acc[j];
        __half hi = __float2half_rn(a);
        size_t o = (size_t)row * HID + lane + 32 * j;
        g_ahi[o] = hi;
        g_alo[o] = __float2half_rn(a - __half2float(hi));
    }
}

// ---------------- launch ----------------
extern "C" void kernel_launch(void* const* d_in, const int* in_sizes, int n_in,
                              void* d_out, int out_size)
{
    const float* h  = (const float*)d_in[0];
    const float* Wq = (const float*)d_in[1];
    const float* bq = (const float*)d_in[2];
    const float* Wk = (const float*)d_in[3];
    const float* bk = (const float*)d_in[4];
    const float* Wv = (const float*)d_in[5];
    const float* bv = (const float*)d_in[6];
    const float* Wo = (const float*)d_in[7];
    const float* bo = (const float*)d_in[8];
    const int* rows = (const int*)d_in[9];
    const int* cols = (const int*)d_in[10];
    (void)n_in; (void)out_size;

    int n = in_sizes[0] / HID;   // 20000
    int e = in_sizes[9];         // 320000
    float* out = (float*)d_out;

    cudaFuncSetAttribute(k_gemm_qkv_mma, cudaFuncAttributeMaxDynamicSharedMemorySize, GEMM_SMEM_DYN);
    cudaFuncSetAttribute(k_gemm_out_mma, cudaFuncAttributeMaxDynamicSharedMemorySize, GEMM_SMEM_DYN);

    int mtiles = (n + 127) / 128;

    // order chosen so ncu -s 5 -c 1 profiles the QKV tensor GEMM
    k_conv_h<<<(n * HID + 255) / 256, 256>>>(h, n * HID);                        // 0
    k_conv_w<<<dim3(HID * HID / 256, 4), 256>>>(Wq, Wk, Wv, Wo);                 // 1
    k_zero<<<(n + 255) / 256, 256>>>(n);                                          // 2
    k_hist<<<(e + 255) / 256, 256>>>(rows, e);                                    // 3
    k_scan<<<1, 1024>>>(n);                                                       // 4
    k_gemm_qkv_mma<<<dim3(2, mtiles, 3), 256, GEMM_SMEM_DYN>>>(bq, bk, bv, n);    // 5 <- profiled
    k_scatter<<<(e + 255) / 256, 256>>>(rows, cols, e);                           // 6
    k_row<<<(n * 32 + 255) / 256, 256>>>(n);                                      // 7
    k_gemm_out_mma<<<dim3(2, mtiles), 256, GEMM_SMEM_DYN>>>(bo, out, n);          // 8
}